// round 2
// baseline (speedup 1.0000x reference)
#include <cuda_runtime.h>
#include <cstdint>
#include <cstddef>

#define BB   8
#define NN   4096
#define KK   32
#define DD   64
#define CIN  67      // D + 3
#define MLPC 64
#define P1C  128
#define P2C  64
#define R2   0.04f   // f32-rounded radius^2, matches reference constant
#define EPSF 1e-5f

// Scratch (device globals; no allocation allowed)
__device__ float  Tp_g[BB * NN * MLPC];   // s[o]*(pts·Wd + xyz·Wx + b), n-major rows
__device__ float4 P4_g[BB * NN];          // (x, y, z, x^2+y^2+z^2)
__device__ float  np_g[BB * NN * MLPC];   // max-pooled features, n-major rows

// ---------------------------------------------------------------------------
// K1: precompute Tp rows + packed candidate table
// ---------------------------------------------------------------------------
__global__ __launch_bounds__(128) void k_pre(
    const float* __restrict__ xyz, const float* __restrict__ pts,
    const float* __restrict__ W,   const float* __restrict__ bcv,
    const float* __restrict__ g,   const float* __restrict__ rv)
{
    __shared__ float Wsh[MLPC * 68];   // rows padded 67 -> 68
    __shared__ float s_sh[MLPC];
    __shared__ float b_sh[MLPC];

    int tid = threadIdx.x;
    for (int i = tid; i < MLPC * CIN; i += 128)
        Wsh[(i / CIN) * 68 + (i % CIN)] = W[i];
    if (tid < MLPC) {
        s_sh[tid] = g[tid] / sqrtf(rv[tid] + EPSF);
        b_sh[tid] = bcv[tid];
    }
    __syncthreads();

    int gm = blockIdx.x * 128 + tid;          // global point id in [0, B*N)
    int b  = gm >> 12;
    int m  = gm & (NN - 1);

    float v[CIN];
#pragma unroll
    for (int d = 0; d < DD; d++) v[d] = pts[(b * DD + d) * NN + m];
#pragma unroll
    for (int j = 0; j < 3; j++)  v[DD + j] = xyz[(b * 3 + j) * NN + m];

    float sq = fmaf(v[66], v[66], fmaf(v[65], v[65], v[64] * v[64]));
    P4_g[gm] = make_float4(v[64], v[65], v[66], sq);

    float* outrow = &Tp_g[(size_t)gm * MLPC];
    for (int o = 0; o < MLPC; o += 4) {
        float tmp[4];
#pragma unroll
        for (int u = 0; u < 4; u++) {
            float acc = b_sh[o + u];
#pragma unroll
            for (int c = 0; c < CIN; c++)
                acc = fmaf(Wsh[(o + u) * 68 + c], v[c], acc);
            tmp[u] = s_sh[o + u] * acc;
        }
        *(float4*)(outrow + o) = make_float4(tmp[0], tmp[1], tmp[2], tmp[3]);
    }
}

// ---------------------------------------------------------------------------
// K2: ball query (first 32 by index within radius) fused with gather-max
// 32 warps/block = 32 queries of one batch; block-staged candidate chunks.
// ---------------------------------------------------------------------------
__global__ __launch_bounds__(1024, 1) void k_ball(
    const float* __restrict__ W,  const float* __restrict__ g,
    const float* __restrict__ bt, const float* __restrict__ rm,
    const float* __restrict__ rv)
{
    __shared__ float4 chunk[1024];        // 16 KB candidate stage
    __shared__ float4 sC4[MLPC];          // {s*Wx0, s*Wx1, s*Wx2, bt - s*rm}
    __shared__ int    gi_sh[32 * KK];     // neighbor lists, per warp
    __shared__ int    sh_done;

    int tid  = threadIdx.x;
    int w    = tid >> 5;
    int lane = tid & 31;

    if (tid == 0) sh_done = 0;
    if (tid < MLPC) {
        float s = g[tid] / sqrtf(rv[tid] + EPSF);
        sC4[tid] = make_float4(s * W[tid * CIN + 64],
                               s * W[tid * CIN + 65],
                               s * W[tid * CIN + 66],
                               bt[tid] - s * rm[tid]);
    }

    int b = blockIdx.x >> 7;                       // 128 blocks per batch
    int n = ((blockIdx.x & 127) << 5) + w;
    float4 q = P4_g[b * NN + n];                   // uniform per warp

    int  cnt   = 0;
    bool wdone = false;

    for (int base = 0; base < NN; base += 1024) {
        __syncthreads();                 // prior chunk consumed; done-flags visible
        if (sh_done >= 32) break;        // uniform across block
        chunk[tid] = P4_g[b * NN + base + tid];
        __syncthreads();

        if (!wdone) {
            for (int it = 0; it < 1024; it += 32) {
                float4 c = chunk[it + lane];
                float dot  = fmaf(q.z, c.z, fmaf(q.y, c.y, q.x * c.x));
                float dist = q.w + c.w - 2.0f * dot;   // reference's exact form
                unsigned mask = __ballot_sync(0xffffffffu, dist <= R2);
                if (mask) {
                    if (dist <= R2) {
                        int pos = cnt + __popc(mask & ((1u << lane) - 1u));
                        if (pos < KK) gi_sh[w * KK + pos] = base + it + lane;
                    }
                    cnt += __popc(mask);
                    if (cnt >= KK) {
                        wdone = true;
                        if (lane == 0) atomicAdd(&sh_done, 1);
                        break;
                    }
                }
            }
        }
    }

    __syncwarp();
    // lanes beyond cnt pad with first neighbor (duplicate => no-op for max)
    int src  = (lane < cnt) ? lane : 0;
    int gidx = gi_sh[w * KK + src];

    // gather-max over 32 neighbors; lane owns channels 2*lane, 2*lane+1
    float2 mx = make_float2(-3.4e38f, -3.4e38f);
#pragma unroll 4
    for (int j = 0; j < KK; j++) {
        int gj = __shfl_sync(0xffffffffu, gidx, j);
        float2 t = *(const float2*)&Tp_g[((size_t)(b * NN + gj)) * MLPC + 2 * lane];
        mx.x = fmaxf(mx.x, t.x);
        mx.y = fmaxf(mx.y, t.y);
    }

    float4 a0 = sC4[2 * lane];
    float4 a1 = sC4[2 * lane + 1];
    float u0 = a0.w - fmaf(a0.z, q.z, fmaf(a0.y, q.y, a0.x * q.x));
    float u1 = a1.w - fmaf(a1.z, q.z, fmaf(a1.y, q.y, a1.x * q.x));

    float2 outv = make_float2(fmaxf(mx.x + u0, 0.0f), fmaxf(mx.y + u1, 0.0f));
    *(float2*)&np_g[((size_t)(b * NN + n)) * MLPC + 2 * lane] = outv;
}

// ---------------------------------------------------------------------------
// K3: pointwise resnet 64 -> 128 -> 64 + residual ReLU. Thread-per-point.
// ---------------------------------------------------------------------------
__global__ __launch_bounds__(128) void k_resnet(
    const float* __restrict__ W1, const float* __restrict__ b1,
    const float* __restrict__ g1, const float* __restrict__ bt1,
    const float* __restrict__ rm1, const float* __restrict__ rv1,
    const float* __restrict__ W2, const float* __restrict__ b2,
    const float* __restrict__ g2, const float* __restrict__ bt2,
    const float* __restrict__ rm2, const float* __restrict__ rv2,
    const float* __restrict__ pts, float* __restrict__ out)
{
    extern __shared__ float sm[];
    float* W1sh  = sm;                  // [128][64] row-major
    float* W2Tsh = sm + P1C * P2C;      // [o][p]  (W2 transposed)
    float* s1sh  = W2Tsh + P1C * P2C;   // 128
    float* t1sh  = s1sh + P1C;          // 128
    float* s2sh  = t1sh + P1C;          // 64
    float* t2sh  = s2sh + P2C;          // 64

    int tid = threadIdx.x;
    for (int i = tid; i < P1C * P2C; i += 128) {
        W1sh[i] = W1[i];
        // W2 is [64][128] row-major: p = i>>7, o = i&127
        W2Tsh[(i & (P1C - 1)) * P2C + (i >> 7)] = W2[i];
    }
    if (tid < P1C) {
        float s = g1[tid] / sqrtf(rv1[tid] + EPSF);
        s1sh[tid] = s;
        t1sh[tid] = fmaf(s, b1[tid] - rm1[tid], bt1[tid]);
    }
    if (tid < P2C) {
        float s = g2[tid] / sqrtf(rv2[tid] + EPSF);
        s2sh[tid] = s;
        t2sh[tid] = fmaf(s, b2[tid] - rm2[tid], bt2[tid]);
    }
    __syncthreads();

    int pt = blockIdx.x * 128 + tid;
    int b  = pt >> 12;
    int n  = pt & (NN - 1);

    float v[P2C];
    const float4* vr = (const float4*)&np_g[(size_t)pt * MLPC];
#pragma unroll
    for (int c4 = 0; c4 < 16; c4++) {
        float4 t = vr[c4];
        v[4 * c4 + 0] = t.x; v[4 * c4 + 1] = t.y;
        v[4 * c4 + 2] = t.z; v[4 * c4 + 3] = t.w;
    }

    float acc[P2C];
#pragma unroll
    for (int p = 0; p < P2C; p++) acc[p] = 0.0f;

    for (int o = 0; o < P1C; o++) {
        float h = 0.0f;
#pragma unroll
        for (int c = 0; c < P2C; c++)
            h = fmaf(W1sh[o * P2C + c], v[c], h);
        float x1 = fmaxf(fmaf(s1sh[o], h, t1sh[o]), 0.0f);
        const float* w2r = &W2Tsh[o * P2C];
#pragma unroll
        for (int p = 0; p < P2C; p++)
            acc[p] = fmaf(w2r[p], x1, acc[p]);
    }

#pragma unroll
    for (int p = 0; p < P2C; p++) {
        float val = fmaf(s2sh[p], acc[p], t2sh[p]) + pts[(b * P2C + p) * NN + n];
        out[(b * P2C + p) * NN + n] = fmaxf(val, 0.0f);
    }
}

// ---------------------------------------------------------------------------
// Launch
// ---------------------------------------------------------------------------
extern "C" void kernel_launch(void* const* d_in, const int* in_sizes, int n_in,
                              void* d_out, int out_size)
{
    const float* xyz = (const float*)d_in[0];
    const float* pts = (const float*)d_in[1];
    const float* W   = (const float*)d_in[2];
    const float* bcv = (const float*)d_in[3];
    const float* g   = (const float*)d_in[4];
    const float* bt  = (const float*)d_in[5];
    const float* rm  = (const float*)d_in[6];
    const float* rv  = (const float*)d_in[7];
    const float* W1  = (const float*)d_in[8];
    const float* b1  = (const float*)d_in[9];
    const float* g1  = (const float*)d_in[10];
    const float* bt1 = (const float*)d_in[11];
    const float* rm1 = (const float*)d_in[12];
    const float* rv1 = (const float*)d_in[13];
    const float* W2  = (const float*)d_in[14];
    const float* b2  = (const float*)d_in[15];
    const float* g2  = (const float*)d_in[16];
    const float* bt2 = (const float*)d_in[17];
    const float* rm2 = (const float*)d_in[18];
    const float* rv2 = (const float*)d_in[19];

    float* out = (float*)d_out;

    static const size_t smem3 =
        (size_t)(P1C * P2C * 2 + P1C * 2 + P2C * 2) * sizeof(float); // 67072 B
    cudaFuncSetAttribute(k_resnet, cudaFuncAttributeMaxDynamicSharedMemorySize,
                         (int)smem3);

    // output tuple = (xyz, out): copy xyz first
    cudaMemcpyAsync(out, xyz, (size_t)in_sizes[0] * sizeof(float),
                    cudaMemcpyDeviceToDevice, 0);

    k_pre<<<(BB * NN) / 128, 128>>>(xyz, pts, W, bcv, g, rv);
    k_ball<<<(BB * NN) / 32, 1024>>>(W, g, bt, rm, rv);
    k_resnet<<<(BB * NN) / 128, 128, smem3>>>(
        W1, b1, g1, bt1, rm1, rv1,
        W2, b2, g2, bt2, rm2, rv2,
        pts, out + in_sizes[0]);
}